// round 8
// baseline (speedup 1.0000x reference)
#include <cuda_runtime.h>
#include <cstddef>

// Problem constants (fixed by the reference)
#define B_    4096
#define NIN_  512
#define L_    16
#define N_    512
#define K_    32
#define NOUT_ 256
#define NNEUR_ (L_ * N_ + NOUT_)      // 8448 total neurons
#define MAXG_  16                     // max groups/neuron (<= 64 entries / 4)

// Unified byte buffer, feature-major rows of B_ bytes:
//   rows [0, 512):        x hi-plane  (u16 value >> 8)
//   rows [512, 1024):     x lo-plane  (u16 value & 0xFF)
//   rows [1024, 9216):    hidden activations u8 = round(255*sigmoid)
#define NROWS_ (2 * NIN_ + L_ * N_)   // 9216
__device__ unsigned char g_bytes[(size_t)NROWS_ * B_];

// Per-neuron preprocessed tables (prep_kernel fills these)
__device__ int4  g_offs [(size_t)NNEUR_ * MAXG_];  // 4 byte-offsets per group
__device__ int2  g_wpk  [(size_t)NNEUR_ * MAXG_];  // packed s16x2 weights (lo,hi)
__device__ int   g_ng   [NNEUR_];                  // group count
__device__ float g_scale[NNEUR_];                  // s/32767
__device__ float g_badj [NNEUR_];                  // bias + offset correction

__device__ __forceinline__ float tanhapx_(float x) {
    float r; asm("tanh.approx.f32 %0, %1;" : "=f"(r) : "f"(x)); return r;
}
__device__ __forceinline__ unsigned prmt_(unsigned a, unsigned b, unsigned sel) {
    unsigned d; asm("prmt.b32 %0, %1, %2, %3;" : "=r"(d) : "r"(a), "r"(b), "r"(sel));
    return d;
}
__device__ __forceinline__ void dp2a_lo_(int& acc, int a, unsigned b) {
    asm("dp2a.lo.s32.u32 %0, %1, %2, %0;" : "+r"(acc) : "r"(a), "r"(b));
}
__device__ __forceinline__ void dp2a_hi_(int& acc, int a, unsigned b) {
    asm("dp2a.hi.s32.u32 %0, %1, %2, %0;" : "+r"(acc) : "r"(a), "r"(b));
}

// 4x4 byte transpose (A,B,C,D = 4 feature words, 4 batch bytes each) + dp2a.
__device__ __forceinline__ void tblock_(int* acc, unsigned A, unsigned Bw,
                                        unsigned C, unsigned D, int wlo, int whi) {
    unsigned t0 = prmt_(A, Bw, 0x5140u);
    unsigned t1 = prmt_(C, D,  0x5140u);
    unsigned t2 = prmt_(A, Bw, 0x7362u);
    unsigned t3 = prmt_(C, D,  0x7362u);
    unsigned b0 = prmt_(t0, t1, 0x5410u);
    unsigned b1 = prmt_(t0, t1, 0x7632u);
    unsigned b2 = prmt_(t2, t3, 0x5410u);
    unsigned b3 = prmt_(t2, t3, 0x7632u);
    dp2a_lo_(acc[0], wlo, b0); dp2a_hi_(acc[0], whi, b0);
    dp2a_lo_(acc[1], wlo, b1); dp2a_hi_(acc[1], whi, b1);
    dp2a_lo_(acc[2], wlo, b2); dp2a_hi_(acc[2], whi, b2);
    dp2a_lo_(acc[3], wlo, b3); dp2a_hi_(acc[3], whi, b3);
}

// Gather core: 8 batch elems (byte offset q8), int32 accumulators iacc[8].
__device__ __forceinline__ void gather_i8_(int* iacc, const int4* s_offs,
                                           const int2* s_wpk, int ng, int q8) {
    const char* __restrict__ gb = reinterpret_cast<const char*>(g_bytes);
    for (int g = 0; g < ng; ++g) {
        const int4 of = s_offs[g];
        const int2 wp = s_wpk[g];
        const uint2 v0 = *reinterpret_cast<const uint2*>(gb + of.x + q8);
        const uint2 v1 = *reinterpret_cast<const uint2*>(gb + of.y + q8);
        const uint2 v2 = *reinterpret_cast<const uint2*>(gb + of.z + q8);
        const uint2 v3 = *reinterpret_cast<const uint2*>(gb + of.w + q8);
        tblock_(iacc + 0, v0.x, v1.x, v2.x, v3.x, wp.x, wp.y);
        tblock_(iacc + 4, v0.y, v1.y, v2.y, v3.y, wp.x, wp.y);
    }
}

// ---------------------------------------------------------------------------
// Prep: per neuron, expand entries (x -> hi+lo planes), fold plane constants
// into s16 weight codes with per-neuron scale, pack into groups of 4.
// ---------------------------------------------------------------------------
__global__ void prep_kernel(const int* __restrict__ idx, const float* __restrict__ W,
                            const float* __restrict__ b,
                            const int* __restrict__ idx_out, const float* __restrict__ W_out,
                            const float* __restrict__ b_out) {
    const int t = blockIdx.x * blockDim.x + threadIdx.x;
    if (t >= NNEUR_) return;
    const int* ip; const float* wp; float bias;
    if (t < L_ * N_) { ip = idx + (size_t)t * K_;  wp = W + (size_t)t * K_;  bias = b[t]; }
    else { const int u = t - L_ * N_;
           ip = idx_out + (size_t)u * K_;  wp = W_out + (size_t)u * K_;  bias = b_out[u]; }

    int   eoff[2 * K_];
    float ecf [2 * K_];
    int ne = 0;
    float corr = 0.f;
    for (int k = 0; k < K_; ++k) {
        const int f = ip[k];
        const float w = wp[k];
        if (f < NIN_) {
            eoff[ne] = f * B_;             ecf[ne++] = w * (1.0f / 16.0f);    // hi plane
            eoff[ne] = (NIN_ + f) * B_;    ecf[ne++] = w * (1.0f / 4096.0f);  // lo plane
            corr -= 8.0f * w;
        } else {
            eoff[ne] = (2 * NIN_ + (f - NIN_)) * B_;  ecf[ne++] = w * (1.0f / 255.0f);
        }
    }
    float s = 0.f;
    for (int i = 0; i < ne; ++i) s = fmaxf(s, fabsf(ecf[i]));
    if (s == 0.f) s = 1.f;
    const float inv = 32767.0f / s;
    while (ne & 3) { eoff[ne] = 0; ecf[ne] = 0.f; ++ne; }
    const int ng = ne >> 2;
    for (int g = 0; g < ng; ++g) {
        int4 o4;
        o4.x = eoff[4 * g];     o4.y = eoff[4 * g + 1];
        o4.z = eoff[4 * g + 2]; o4.w = eoff[4 * g + 3];
        int q[4];
#pragma unroll
        for (int j = 0; j < 4; ++j) {
            int v = __float2int_rn(ecf[4 * g + j] * inv);
            q[j] = max(-32767, min(32767, v));
        }
        int2 wpk;
        wpk.x = (q[1] << 16) | (q[0] & 0xFFFF);
        wpk.y = (q[3] << 16) | (q[2] & 0xFFFF);
        g_offs[(size_t)t * MAXG_ + g] = o4;
        g_wpk [(size_t)t * MAXG_ + g] = wpk;
    }
    g_ng[t]    = ng;
    g_scale[t] = s / 32767.0f;
    g_badj[t]  = bias + corr;
}

// ---------------------------------------------------------------------------
// Transpose x (B, NIN) f32 -> two u8 planes (feature-major), u16 = (x+8)*4096
// ---------------------------------------------------------------------------
__global__ void __launch_bounds__(1024) transpose_in_kernel(const float* __restrict__ x) {
    __shared__ float tile[32][33];
    const int f0 = blockIdx.x * 32;
    const int b0 = blockIdx.y * 32;
    tile[threadIdx.y][threadIdx.x] = x[(size_t)(b0 + threadIdx.y) * NIN_ + (f0 + threadIdx.x)];
    __syncthreads();
    const float xv = tile[threadIdx.x][threadIdx.y];
    float vf = fminf(fmaxf((xv + 8.0f) * 4096.0f, 0.0f), 65535.0f);
    const unsigned u = __float2uint_rn(vf);
    const int f = f0 + threadIdx.y;
    const int bb = b0 + threadIdx.x;
    g_bytes[(size_t)f * B_ + bb]           = (unsigned char)(u >> 8);
    g_bytes[(size_t)(NIN_ + f) * B_ + bb]  = (unsigned char)(u & 0xFF);
}

// ---------------------------------------------------------------------------
// One sparse layer. block (32,8): warp = one neuron, 32 tx x 8 batch = 256.
// grid (16, 64) = 1024 blocks; 6 blocks/SM target.
// ---------------------------------------------------------------------------
__global__ void __launch_bounds__(256, 6) layer_kernel(int l) {
    __shared__ int4  s_offs[8][MAXG_];
    __shared__ int2  s_wpk [8][MAXG_];
    __shared__ int   s_ng[8];
    __shared__ float s_sc[8], s_ba[8];
    const int tx = threadIdx.x, ty = threadIdx.y;
    const int n  = blockIdx.y * 8 + ty;
    const int gn = l * N_ + n;

    if (tx < MAXG_)            s_offs[ty][tx]         = g_offs[(size_t)gn * MAXG_ + tx];
    else if (tx < 2 * MAXG_)   s_wpk [ty][tx - MAXG_] = g_wpk [(size_t)gn * MAXG_ + (tx - MAXG_)];
    if (tx == 0) { s_ng[ty] = g_ng[gn]; s_sc[ty] = g_scale[gn]; s_ba[ty] = g_badj[gn]; }
    __syncthreads();

    const int q8 = (blockIdx.x * 32 + tx) * 8;

    int iacc[8];
#pragma unroll
    for (int i = 0; i < 8; ++i) iacc[i] = 0;

    gather_i8_(iacc, s_offs[ty], s_wpk[ty], s_ng[ty], q8);

    const float sc = s_sc[ty];
    const float ba = s_ba[ty];
    unsigned bytes[8];
#pragma unroll
    for (int i = 0; i < 8; ++i) {
        const float pre = fmaf((float)iacc[i], sc, ba);
        const float th  = tanhapx_(0.5f * pre);                 // sigmoid = .5+.5*tanh(v/2)
        bytes[i] = __float2uint_rn(fmaf(th, 127.5f, 127.5f));   // round(255*sigmoid)
    }
    uint2 o;
    {
        unsigned lo0 = __byte_perm(bytes[0], bytes[1], 0x0040);
        unsigned hi0 = __byte_perm(bytes[2], bytes[3], 0x0040);
        unsigned lo1 = __byte_perm(bytes[4], bytes[5], 0x0040);
        unsigned hi1 = __byte_perm(bytes[6], bytes[7], 0x0040);
        o.x = __byte_perm(lo0, hi0, 0x5410);
        o.y = __byte_perm(lo1, hi1, 0x5410);
    }
    *reinterpret_cast<uint2*>(g_bytes + (size_t)(2 * NIN_ + gn) * B_ + q8) = o;
}

// ---------------------------------------------------------------------------
// Output layer. block (32,8), grid (16, 32) = 512 blocks. Exact sigmoid,
// f32 out, smem transpose so each thread stores full 32B sectors.
// ---------------------------------------------------------------------------
__global__ void __launch_bounds__(256, 6) out_kernel(float* __restrict__ out) {
    __shared__ int4  s_offs[8][MAXG_];
    __shared__ int2  s_wpk [8][MAXG_];
    __shared__ int   s_ng[8];
    __shared__ float s_sc[8], s_ba[8];
    __shared__ float tile[8][256];
    const int tx = threadIdx.x, ty = threadIdx.y;
    const int o0 = blockIdx.y * 8;
    const int o  = o0 + ty;
    const int gn = L_ * N_ + o;

    if (tx < MAXG_)            s_offs[ty][tx]         = g_offs[(size_t)gn * MAXG_ + tx];
    else if (tx < 2 * MAXG_)   s_wpk [ty][tx - MAXG_] = g_wpk [(size_t)gn * MAXG_ + (tx - MAXG_)];
    if (tx == 0) { s_ng[ty] = g_ng[gn]; s_sc[ty] = g_scale[gn]; s_ba[ty] = g_badj[gn]; }
    __syncthreads();

    const int q8 = (blockIdx.x * 32 + tx) * 8;

    int iacc[8];
#pragma unroll
    for (int i = 0; i < 8; ++i) iacc[i] = 0;

    gather_i8_(iacc, s_offs[ty], s_wpk[ty], s_ng[ty], q8);

    const float sc = s_sc[ty];
    const float ba = s_ba[ty];
    const int bl = tx * 8;
#pragma unroll
    for (int i = 0; i < 8; ++i) {
        const float pre = fmaf((float)iacc[i], sc, ba);
        tile[ty][bl + i] = 1.0f / (1.0f + __expf(-pre));
    }
    __syncthreads();

    const int t = ty * 32 + tx;
    const int b = blockIdx.x * 256 + t;
    float4 w0, w1;
    w0.x = tile[0][t]; w0.y = tile[1][t]; w0.z = tile[2][t]; w0.w = tile[3][t];
    w1.x = tile[4][t]; w1.y = tile[5][t]; w1.z = tile[6][t]; w1.w = tile[7][t];
    float4* dst = reinterpret_cast<float4*>(out + (size_t)b * NOUT_ + o0);
    dst[0] = w0;
    dst[1] = w1;
}

// ---------------------------------------------------------------------------
// kernel_launch: inputs in metadata order:
//   0: x (B,NIN) f32   1: W (L,N,K) f32   2: b (L,N) f32
//   3: W_out (NOUT,K) f32   4: b_out (NOUT,) f32
//   5: idx (L,N,K) i32      6: idx_out (NOUT,K) i32
// ---------------------------------------------------------------------------
extern "C" void kernel_launch(void* const* d_in, const int* in_sizes, int n_in,
                              void* d_out, int out_size) {
    const float* x     = (const float*)d_in[0];
    const float* W     = (const float*)d_in[1];
    const float* b     = (const float*)d_in[2];
    const float* W_out = (const float*)d_in[3];
    const float* b_out = (const float*)d_in[4];
    const int*   idx     = (const int*)d_in[5];
    const int*   idx_out = (const int*)d_in[6];
    float* out = (float*)d_out;

    prep_kernel<<<(NNEUR_ + 255) / 256, 256>>>(idx, W, b, idx_out, W_out, b_out);
    {
        dim3 blk(32, 32);
        dim3 grd(NIN_ / 32, B_ / 32);
        transpose_in_kernel<<<grd, blk>>>(x);
    }
    {
        dim3 blk(32, 8);
        dim3 grd(16, N_ / 8);
        for (int l = 0; l < L_; ++l) layer_kernel<<<grd, blk>>>(l);
    }
    {
        dim3 blk(32, 8);
        dim3 grd(16, NOUT_ / 8);
        out_kernel<<<grd, blk>>>(out);
    }
}

// round 9
// speedup vs baseline: 1.1700x; 1.1700x over previous
#include <cuda_runtime.h>
#include <cstddef>

// Problem constants (fixed by the reference)
#define B_    4096
#define NIN_  512
#define L_    16
#define N_    512
#define K_    32
#define NOUT_ 256
#define NNEUR_ (L_ * N_ + NOUT_)      // 8448 total neurons
#define MAXG_  16                     // max groups/neuron (<= 64 entries / 4)

// Unified byte buffer, feature-major rows of B_ bytes:
//   rows [0, 512):        x hi-plane  (u16 value >> 8)
//   rows [512, 1024):     x lo-plane  (u16 value & 0xFF)
//   rows [1024, 9216):    hidden activations u8 = round(255*sigmoid)
#define NROWS_ (2 * NIN_ + L_ * N_)   // 9216
__device__ unsigned char g_bytes[(size_t)NROWS_ * B_];

// Per-neuron preprocessed tables (prep_kernel fills these)
__device__ int4  g_offs [(size_t)NNEUR_ * MAXG_];  // 4 byte-offsets per group
__device__ int2  g_wpk  [(size_t)NNEUR_ * MAXG_];  // packed s16x2 weights (lo,hi)
__device__ int   g_ng   [NNEUR_];                  // group count
__device__ float g_scale[NNEUR_];                  // s/32767
__device__ float g_badj [NNEUR_];                  // bias + offset correction

__device__ __forceinline__ float tanhapx_(float x) {
    float r; asm("tanh.approx.f32 %0, %1;" : "=f"(r) : "f"(x)); return r;
}
__device__ __forceinline__ unsigned prmt_(unsigned a, unsigned b, unsigned sel) {
    unsigned d; asm("prmt.b32 %0, %1, %2, %3;" : "=r"(d) : "r"(a), "r"(b), "r"(sel));
    return d;
}
__device__ __forceinline__ void dp2a_lo_(int& acc, int a, unsigned b) {
    asm("dp2a.lo.s32.u32 %0, %1, %2, %0;" : "+r"(acc) : "r"(a), "r"(b));
}
__device__ __forceinline__ void dp2a_hi_(int& acc, int a, unsigned b) {
    asm("dp2a.hi.s32.u32 %0, %1, %2, %0;" : "+r"(acc) : "r"(a), "r"(b));
}

// 4x4 byte transpose (A,B,C,D = 4 feature words, 4 batch bytes each) + dp2a.
__device__ __forceinline__ void tblock_(int* acc, unsigned A, unsigned Bw,
                                        unsigned C, unsigned D, int wlo, int whi) {
    unsigned t0 = prmt_(A, Bw, 0x5140u);
    unsigned t1 = prmt_(C, D,  0x5140u);
    unsigned t2 = prmt_(A, Bw, 0x7362u);
    unsigned t3 = prmt_(C, D,  0x7362u);
    unsigned b0 = prmt_(t0, t1, 0x5410u);
    unsigned b1 = prmt_(t0, t1, 0x7632u);
    unsigned b2 = prmt_(t2, t3, 0x5410u);
    unsigned b3 = prmt_(t2, t3, 0x7632u);
    dp2a_lo_(acc[0], wlo, b0); dp2a_hi_(acc[0], whi, b0);
    dp2a_lo_(acc[1], wlo, b1); dp2a_hi_(acc[1], whi, b1);
    dp2a_lo_(acc[2], wlo, b2); dp2a_hi_(acc[2], whi, b2);
    dp2a_lo_(acc[3], wlo, b3); dp2a_hi_(acc[3], whi, b3);
}

// Gather core: 16 batch elems (byte offset q16), int32 accumulators iacc[16].
__device__ __forceinline__ void gather_i8_(int* iacc, const int4* s_offs,
                                           const int2* s_wpk, int ng, int q16) {
    const char* __restrict__ gb = reinterpret_cast<const char*>(g_bytes);
    for (int g = 0; g < ng; ++g) {
        const int4 of = s_offs[g];
        const int2 wp = s_wpk[g];
        const uint4 v0 = *reinterpret_cast<const uint4*>(gb + of.x + q16);
        const uint4 v1 = *reinterpret_cast<const uint4*>(gb + of.y + q16);
        const uint4 v2 = *reinterpret_cast<const uint4*>(gb + of.z + q16);
        const uint4 v3 = *reinterpret_cast<const uint4*>(gb + of.w + q16);
        tblock_(iacc + 0,  v0.x, v1.x, v2.x, v3.x, wp.x, wp.y);
        tblock_(iacc + 4,  v0.y, v1.y, v2.y, v3.y, wp.x, wp.y);
        tblock_(iacc + 8,  v0.z, v1.z, v2.z, v3.z, wp.x, wp.y);
        tblock_(iacc + 12, v0.w, v1.w, v2.w, v3.w, wp.x, wp.y);
    }
}

// ---------------------------------------------------------------------------
// Prep: per neuron, expand entries (x -> hi+lo planes), fold plane constants
// into s16 weight codes with per-neuron scale, pack into groups of 4.
// ---------------------------------------------------------------------------
__global__ void prep_kernel(const int* __restrict__ idx, const float* __restrict__ W,
                            const float* __restrict__ b,
                            const int* __restrict__ idx_out, const float* __restrict__ W_out,
                            const float* __restrict__ b_out) {
    const int t = blockIdx.x * blockDim.x + threadIdx.x;
    if (t >= NNEUR_) return;
    const int* ip; const float* wp; float bias;
    if (t < L_ * N_) { ip = idx + (size_t)t * K_;  wp = W + (size_t)t * K_;  bias = b[t]; }
    else { const int u = t - L_ * N_;
           ip = idx_out + (size_t)u * K_;  wp = W_out + (size_t)u * K_;  bias = b_out[u]; }

    int   eoff[2 * K_];
    float ecf [2 * K_];
    int ne = 0;
    float corr = 0.f;
    for (int k = 0; k < K_; ++k) {
        const int f = ip[k];
        const float w = wp[k];
        if (f < NIN_) {
            eoff[ne] = f * B_;             ecf[ne++] = w * (1.0f / 16.0f);    // hi plane
            eoff[ne] = (NIN_ + f) * B_;    ecf[ne++] = w * (1.0f / 4096.0f);  // lo plane
            corr -= 8.0f * w;
        } else {
            eoff[ne] = (2 * NIN_ + (f - NIN_)) * B_;  ecf[ne++] = w * (1.0f / 255.0f);
        }
    }
    float s = 0.f;
    for (int i = 0; i < ne; ++i) s = fmaxf(s, fabsf(ecf[i]));
    if (s == 0.f) s = 1.f;
    const float inv = 32767.0f / s;
    while (ne & 3) { eoff[ne] = 0; ecf[ne] = 0.f; ++ne; }
    const int ng = ne >> 2;
    for (int g = 0; g < ng; ++g) {
        int4 o4;
        o4.x = eoff[4 * g];     o4.y = eoff[4 * g + 1];
        o4.z = eoff[4 * g + 2]; o4.w = eoff[4 * g + 3];
        int q[4];
#pragma unroll
        for (int j = 0; j < 4; ++j) {
            int v = __float2int_rn(ecf[4 * g + j] * inv);
            q[j] = max(-32767, min(32767, v));
        }
        int2 wpk;
        wpk.x = (q[1] << 16) | (q[0] & 0xFFFF);
        wpk.y = (q[3] << 16) | (q[2] & 0xFFFF);
        g_offs[(size_t)t * MAXG_ + g] = o4;
        g_wpk [(size_t)t * MAXG_ + g] = wpk;
    }
    g_ng[t]    = ng;
    g_scale[t] = s / 32767.0f;
    g_badj[t]  = bias + corr;
}

// ---------------------------------------------------------------------------
// Transpose x (B, NIN) f32 -> two u8 planes (feature-major), u16 = (x+8)*4096
// ---------------------------------------------------------------------------
__global__ void __launch_bounds__(1024) transpose_in_kernel(const float* __restrict__ x) {
    __shared__ float tile[32][33];
    const int f0 = blockIdx.x * 32;
    const int b0 = blockIdx.y * 32;
    tile[threadIdx.y][threadIdx.x] = x[(size_t)(b0 + threadIdx.y) * NIN_ + (f0 + threadIdx.x)];
    __syncthreads();
    const float xv = tile[threadIdx.x][threadIdx.y];
    float vf = fminf(fmaxf((xv + 8.0f) * 4096.0f, 0.0f), 65535.0f);
    const unsigned u = __float2uint_rn(vf);
    const int f = f0 + threadIdx.y;
    const int bb = b0 + threadIdx.x;
    g_bytes[(size_t)f * B_ + bb]           = (unsigned char)(u >> 8);
    g_bytes[(size_t)(NIN_ + f) * B_ + bb]  = (unsigned char)(u & 0xFF);
}

// ---------------------------------------------------------------------------
// One sparse layer. block (32,4): warp = one neuron, 32 tx x 16 batch = 512.
// grid (8, 128) = 1024 blocks of 128 threads; 8 blocks/SM theoretical.
// ---------------------------------------------------------------------------
__global__ void __launch_bounds__(128, 8) layer_kernel(int l) {
    __shared__ int4  s_offs[4][MAXG_];
    __shared__ int2  s_wpk [4][MAXG_];
    __shared__ int   s_ng[4];
    __shared__ float s_sc[4], s_ba[4];
    const int tx = threadIdx.x, ty = threadIdx.y;
    const int n  = blockIdx.y * 4 + ty;
    const int gn = l * N_ + n;

    if (tx < MAXG_)            s_offs[ty][tx]         = g_offs[(size_t)gn * MAXG_ + tx];
    else if (tx < 2 * MAXG_)   s_wpk [ty][tx - MAXG_] = g_wpk [(size_t)gn * MAXG_ + (tx - MAXG_)];
    if (tx == 0) { s_ng[ty] = g_ng[gn]; s_sc[ty] = g_scale[gn]; s_ba[ty] = g_badj[gn]; }
    __syncthreads();

    const int q16 = (blockIdx.x * 32 + tx) * 16;

    int iacc[16];
#pragma unroll
    for (int i = 0; i < 16; ++i) iacc[i] = 0;

    gather_i8_(iacc, s_offs[ty], s_wpk[ty], s_ng[ty], q16);

    const float sc = s_sc[ty];
    const float ba = s_ba[ty];
    unsigned bytes[16];
#pragma unroll
    for (int i = 0; i < 16; ++i) {
        const float pre = fmaf((float)iacc[i], sc, ba);
        const float th  = tanhapx_(0.5f * pre);                 // sigmoid = .5+.5*tanh(v/2)
        bytes[i] = __float2uint_rn(fmaf(th, 127.5f, 127.5f));   // round(255*sigmoid)
    }
    uint4 o;
    unsigned* ow = &o.x;
#pragma unroll
    for (int i = 0; i < 4; ++i) {
        unsigned lo = __byte_perm(bytes[4 * i],     bytes[4 * i + 1], 0x0040);
        unsigned hi = __byte_perm(bytes[4 * i + 2], bytes[4 * i + 3], 0x0040);
        ow[i] = __byte_perm(lo, hi, 0x5410);
    }
    *reinterpret_cast<uint4*>(g_bytes + (size_t)(2 * NIN_ + gn) * B_ + q16) = o;
}

// ---------------------------------------------------------------------------
// Output layer. block (32,4), grid (8, 64) = 512 blocks. Exact sigmoid,
// f32 out, smem transpose so each thread stores full 32B sectors.
// ---------------------------------------------------------------------------
__global__ void __launch_bounds__(128, 8) out_kernel(float* __restrict__ out) {
    __shared__ int4  s_offs[4][MAXG_];
    __shared__ int2  s_wpk [4][MAXG_];
    __shared__ int   s_ng[4];
    __shared__ float s_sc[4], s_ba[4];
    __shared__ float tile[4][512];
    const int tx = threadIdx.x, ty = threadIdx.y;
    const int o0 = blockIdx.y * 4;
    const int o  = o0 + ty;
    const int gn = L_ * N_ + o;

    if (tx < MAXG_)            s_offs[ty][tx]         = g_offs[(size_t)gn * MAXG_ + tx];
    else if (tx < 2 * MAXG_)   s_wpk [ty][tx - MAXG_] = g_wpk [(size_t)gn * MAXG_ + (tx - MAXG_)];
    if (tx == 0) { s_ng[ty] = g_ng[gn]; s_sc[ty] = g_scale[gn]; s_ba[ty] = g_badj[gn]; }
    __syncthreads();

    const int q16 = (blockIdx.x * 32 + tx) * 16;

    int iacc[16];
#pragma unroll
    for (int i = 0; i < 16; ++i) iacc[i] = 0;

    gather_i8_(iacc, s_offs[ty], s_wpk[ty], s_ng[ty], q16);

    const float sc = s_sc[ty];
    const float ba = s_ba[ty];
    const int bl = tx * 16;
#pragma unroll
    for (int i = 0; i < 16; ++i) {
        const float pre = fmaf((float)iacc[i], sc, ba);
        tile[ty][bl + i] = 1.0f / (1.0f + __expf(-pre));
    }
    __syncthreads();

    // 512 local batch rows, 128 threads -> 4 rows each; 4 consecutive f32 (16B) per row
    const int t = ty * 32 + tx;
    const int bbase = blockIdx.x * 512;
#pragma unroll
    for (int r = 0; r < 4; ++r) {
        const int lb = t + r * 128;
        float4 w0;
        w0.x = tile[0][lb]; w0.y = tile[1][lb]; w0.z = tile[2][lb]; w0.w = tile[3][lb];
        *reinterpret_cast<float4*>(out + (size_t)(bbase + lb) * NOUT_ + o0) = w0;
    }
}

// ---------------------------------------------------------------------------
// kernel_launch: inputs in metadata order:
//   0: x (B,NIN) f32   1: W (L,N,K) f32   2: b (L,N) f32
//   3: W_out (NOUT,K) f32   4: b_out (NOUT,) f32
//   5: idx (L,N,K) i32      6: idx_out (NOUT,K) i32
// ---------------------------------------------------------------------------
extern "C" void kernel_launch(void* const* d_in, const int* in_sizes, int n_in,
                              void* d_out, int out_size) {
    const float* x     = (const float*)d_in[0];
    const float* W     = (const float*)d_in[1];
    const float* b     = (const float*)d_in[2];
    const float* W_out = (const float*)d_in[3];
    const float* b_out = (const float*)d_in[4];
    const int*   idx     = (const int*)d_in[5];
    const int*   idx_out = (const int*)d_in[6];
    float* out = (float*)d_out;

    prep_kernel<<<(NNEUR_ + 255) / 256, 256>>>(idx, W, b, idx_out, W_out, b_out);
    {
        dim3 blk(32, 32);
        dim3 grd(NIN_ / 32, B_ / 32);
        transpose_in_kernel<<<grd, blk>>>(x);
    }
    {
        dim3 blk(32, 4);
        dim3 grd(8, N_ / 4);   // 1024 blocks
        for (int l = 0; l < L_; ++l) layer_kernel<<<grd, blk>>>(l);
    }
    {
        dim3 blk(32, 4);
        dim3 grd(8, NOUT_ / 4);  // 512 blocks
        out_kernel<<<grd, blk>>>(out);
    }
}

// round 10
// speedup vs baseline: 1.2998x; 1.1109x over previous
#include <cuda_runtime.h>
#include <cstddef>

// Problem constants (fixed by the reference)
#define B_    4096
#define NIN_  512
#define L_    16
#define N_    512
#define K_    32
#define NOUT_ 256
#define NNEUR_ (L_ * N_ + NOUT_)      // 8448 total neurons
#define MAXG_  16                     // max groups/neuron (<= 64 entries / 4)

// Unified byte buffer, feature-major rows of B_ bytes:
//   rows [0, 512):        x hi-plane  (u16 value >> 8)
//   rows [512, 1024):     x lo-plane  (u16 value & 0xFF)
//   rows [1024, 9216):    hidden activations u8 = round(255*sigmoid)
#define NROWS_ (2 * NIN_ + L_ * N_)   // 9216
__device__ unsigned char g_bytes[(size_t)NROWS_ * B_];

// Per-neuron preprocessed tables (prep_kernel fills these)
__device__ int4  g_offs [(size_t)NNEUR_ * MAXG_];  // 4 byte-offsets per group
__device__ int2  g_wpk  [(size_t)NNEUR_ * MAXG_];  // packed s16x2 weights ([w0,w1],[w2,w3])
__device__ int   g_ng   [NNEUR_];                  // group count
__device__ float g_scale[NNEUR_];                  // s/32767
__device__ float g_badj [NNEUR_];                  // bias + offset correction

__device__ __forceinline__ float tanhapx_(float x) {
    float r; asm("tanh.approx.f32 %0, %1;" : "=f"(r) : "f"(x)); return r;
}
__device__ __forceinline__ unsigned prmt_(unsigned a, unsigned b, unsigned sel) {
    unsigned d; asm("prmt.b32 %0, %1, %2, %3;" : "=r"(d) : "r"(a), "r"(b), "r"(sel));
    return d;
}
__device__ __forceinline__ void dp2a_lo_(int& acc, int a, unsigned b) {
    asm("dp2a.lo.s32.u32 %0, %1, %2, %0;" : "+r"(acc) : "r"(a), "r"(b));
}
__device__ __forceinline__ void dp2a_hi_(int& acc, int a, unsigned b) {
    asm("dp2a.hi.s32.u32 %0, %1, %2, %0;" : "+r"(acc) : "r"(a), "r"(b));
}

// Pairwise dp2a block: A,B = words of features f0,f1; C,D = words of f2,f3
// (each word = 4 batch bytes). w01 = s16x2 [w0,w1], w23 = [w2,w3].
// 4 prmt + 8 dp2a per 16 MACs (vs 8 prmt + 8 dp2a for a full 4x4 transpose).
__device__ __forceinline__ void tpair_(int* acc, unsigned A, unsigned Bw,
                                       unsigned C, unsigned D, int w01, int w23) {
    unsigned t0 = prmt_(A, Bw, 0x5140u);   // A0,B0,A1,B1
    unsigned t1 = prmt_(A, Bw, 0x7362u);   // A2,B2,A3,B3
    unsigned t2 = prmt_(C, D,  0x5140u);   // C0,D0,C1,D1
    unsigned t3 = prmt_(C, D,  0x7362u);   // C2,D2,C3,D3
    dp2a_lo_(acc[0], w01, t0); dp2a_lo_(acc[0], w23, t2);   // batch 0
    dp2a_hi_(acc[1], w01, t0); dp2a_hi_(acc[1], w23, t2);   // batch 1
    dp2a_lo_(acc[2], w01, t1); dp2a_lo_(acc[2], w23, t3);   // batch 2
    dp2a_hi_(acc[3], w01, t1); dp2a_hi_(acc[3], w23, t3);   // batch 3
}

// Gather core: 16 batch elems (byte offset q16), int32 accumulators iacc[16].
__device__ __forceinline__ void gather_i8_(int* iacc, const int4* s_offs,
                                           const int2* s_wpk, int ng, int q16) {
    const char* __restrict__ gb = reinterpret_cast<const char*>(g_bytes);
    for (int g = 0; g < ng; ++g) {
        const int4 of = s_offs[g];
        const int2 wp = s_wpk[g];
        const uint4 v0 = __ldg(reinterpret_cast<const uint4*>(gb + of.x + q16));
        const uint4 v1 = __ldg(reinterpret_cast<const uint4*>(gb + of.y + q16));
        const uint4 v2 = __ldg(reinterpret_cast<const uint4*>(gb + of.z + q16));
        const uint4 v3 = __ldg(reinterpret_cast<const uint4*>(gb + of.w + q16));
        tpair_(iacc + 0,  v0.x, v1.x, v2.x, v3.x, wp.x, wp.y);
        tpair_(iacc + 4,  v0.y, v1.y, v2.y, v3.y, wp.x, wp.y);
        tpair_(iacc + 8,  v0.z, v1.z, v2.z, v3.z, wp.x, wp.y);
        tpair_(iacc + 12, v0.w, v1.w, v2.w, v3.w, wp.x, wp.y);
    }
}

// ---------------------------------------------------------------------------
// Prep: per neuron, expand entries (x -> hi+lo planes), fold plane constants
// into s16 weight codes with per-neuron scale, pack into groups of 4.
// ---------------------------------------------------------------------------
__global__ void prep_kernel(const int* __restrict__ idx, const float* __restrict__ W,
                            const float* __restrict__ b,
                            const int* __restrict__ idx_out, const float* __restrict__ W_out,
                            const float* __restrict__ b_out) {
    const int t = blockIdx.x * blockDim.x + threadIdx.x;
    if (t >= NNEUR_) return;
    const int* ip; const float* wp; float bias;
    if (t < L_ * N_) { ip = idx + (size_t)t * K_;  wp = W + (size_t)t * K_;  bias = b[t]; }
    else { const int u = t - L_ * N_;
           ip = idx_out + (size_t)u * K_;  wp = W_out + (size_t)u * K_;  bias = b_out[u]; }

    int   eoff[2 * K_];
    float ecf [2 * K_];
    int ne = 0;
    float corr = 0.f;
    for (int k = 0; k < K_; ++k) {
        const int f = ip[k];
        const float w = wp[k];
        if (f < NIN_) {
            eoff[ne] = f * B_;             ecf[ne++] = w * (1.0f / 16.0f);    // hi plane
            eoff[ne] = (NIN_ + f) * B_;    ecf[ne++] = w * (1.0f / 4096.0f);  // lo plane
            corr -= 8.0f * w;
        } else {
            eoff[ne] = (2 * NIN_ + (f - NIN_)) * B_;  ecf[ne++] = w * (1.0f / 255.0f);
        }
    }
    float s = 0.f;
    for (int i = 0; i < ne; ++i) s = fmaxf(s, fabsf(ecf[i]));
    if (s == 0.f) s = 1.f;
    const float inv = 32767.0f / s;
    while (ne & 3) { eoff[ne] = 0; ecf[ne] = 0.f; ++ne; }
    const int ng = ne >> 2;
    for (int g = 0; g < ng; ++g) {
        int4 o4;
        o4.x = eoff[4 * g];     o4.y = eoff[4 * g + 1];
        o4.z = eoff[4 * g + 2]; o4.w = eoff[4 * g + 3];
        int q[4];
#pragma unroll
        for (int j = 0; j < 4; ++j) {
            int v = __float2int_rn(ecf[4 * g + j] * inv);
            q[j] = max(-32767, min(32767, v));
        }
        int2 wpk;
        wpk.x = (q[1] << 16) | (q[0] & 0xFFFF);
        wpk.y = (q[3] << 16) | (q[2] & 0xFFFF);
        g_offs[(size_t)t * MAXG_ + g] = o4;
        g_wpk [(size_t)t * MAXG_ + g] = wpk;
    }
    g_ng[t]    = ng;
    g_scale[t] = s / 32767.0f;
    g_badj[t]  = bias + corr;
}

// ---------------------------------------------------------------------------
// Transpose x (B, NIN) f32 -> two u8 planes (feature-major), u16 = (x+8)*4096
// ---------------------------------------------------------------------------
__global__ void __launch_bounds__(1024) transpose_in_kernel(const float* __restrict__ x) {
    __shared__ float tile[32][33];
    const int f0 = blockIdx.x * 32;
    const int b0 = blockIdx.y * 32;
    tile[threadIdx.y][threadIdx.x] = x[(size_t)(b0 + threadIdx.y) * NIN_ + (f0 + threadIdx.x)];
    __syncthreads();
    const float xv = tile[threadIdx.x][threadIdx.y];
    float vf = fminf(fmaxf((xv + 8.0f) * 4096.0f, 0.0f), 65535.0f);
    const unsigned u = __float2uint_rn(vf);
    const int f = f0 + threadIdx.y;
    const int bb = b0 + threadIdx.x;
    g_bytes[(size_t)f * B_ + bb]           = (unsigned char)(u >> 8);
    g_bytes[(size_t)(NIN_ + f) * B_ + bb]  = (unsigned char)(u & 0xFF);
}

// ---------------------------------------------------------------------------
// One sparse layer. block (32,4): warp = one neuron, 32 tx x 16 batch = 512.
// grid (8, 128) = 1024 blocks of 128 threads.
// ---------------------------------------------------------------------------
__global__ void __launch_bounds__(128, 8) layer_kernel(int l) {
    __shared__ int4  s_offs[4][MAXG_];
    __shared__ int2  s_wpk [4][MAXG_];
    __shared__ int   s_ng[4];
    __shared__ float s_sc[4], s_ba[4];
    const int tx = threadIdx.x, ty = threadIdx.y;
    const int n  = blockIdx.y * 4 + ty;
    const int gn = l * N_ + n;

    if (tx < MAXG_)            s_offs[ty][tx]         = g_offs[(size_t)gn * MAXG_ + tx];
    else if (tx < 2 * MAXG_)   s_wpk [ty][tx - MAXG_] = g_wpk [(size_t)gn * MAXG_ + (tx - MAXG_)];
    if (tx == 0) { s_ng[ty] = g_ng[gn]; s_sc[ty] = g_scale[gn]; s_ba[ty] = g_badj[gn]; }
    __syncthreads();

    const int q16 = (blockIdx.x * 32 + tx) * 16;

    int iacc[16];
#pragma unroll
    for (int i = 0; i < 16; ++i) iacc[i] = 0;

    gather_i8_(iacc, s_offs[ty], s_wpk[ty], s_ng[ty], q16);

    const float sc = s_sc[ty];
    const float ba = s_ba[ty];
    unsigned bytes[16];
#pragma unroll
    for (int i = 0; i < 16; ++i) {
        const float pre = fmaf((float)iacc[i], sc, ba);
        const float th  = tanhapx_(0.5f * pre);                 // sigmoid = .5+.5*tanh(v/2)
        bytes[i] = __float2uint_rn(fmaf(th, 127.5f, 127.5f));   // round(255*sigmoid)
    }
    uint4 o;
    unsigned* ow = &o.x;
#pragma unroll
    for (int i = 0; i < 4; ++i) {
        unsigned lo = __byte_perm(bytes[4 * i],     bytes[4 * i + 1], 0x0040);
        unsigned hi = __byte_perm(bytes[4 * i + 2], bytes[4 * i + 3], 0x0040);
        ow[i] = __byte_perm(lo, hi, 0x5410);
    }
    *reinterpret_cast<uint4*>(g_bytes + (size_t)(2 * NIN_ + gn) * B_ + q16) = o;
}

// ---------------------------------------------------------------------------
// Output layer. block (32,4), grid (8, 64) = 512 blocks. Exact sigmoid,
// f32 out, smem transpose so each thread stores full 16B sectors.
// ---------------------------------------------------------------------------
__global__ void __launch_bounds__(128, 8) out_kernel(float* __restrict__ out) {
    __shared__ int4  s_offs[4][MAXG_];
    __shared__ int2  s_wpk [4][MAXG_];
    __shared__ int   s_ng[4];
    __shared__ float s_sc[4], s_ba[4];
    __shared__ float tile[4][512];
    const int tx = threadIdx.x, ty = threadIdx.y;
    const int o0 = blockIdx.y * 4;
    const int o  = o0 + ty;
    const int gn = L_ * N_ + o;

    if (tx < MAXG_)            s_offs[ty][tx]         = g_offs[(size_t)gn * MAXG_ + tx];
    else if (tx < 2 * MAXG_)   s_wpk [ty][tx - MAXG_] = g_wpk [(size_t)gn * MAXG_ + (tx - MAXG_)];
    if (tx == 0) { s_ng[ty] = g_ng[gn]; s_sc[ty] = g_scale[gn]; s_ba[ty] = g_badj[gn]; }
    __syncthreads();

    const int q16 = (blockIdx.x * 32 + tx) * 16;

    int iacc[16];
#pragma unroll
    for (int i = 0; i < 16; ++i) iacc[i] = 0;

    gather_i8_(iacc, s_offs[ty], s_wpk[ty], s_ng[ty], q16);

    const float sc = s_sc[ty];
    const float ba = s_ba[ty];
    const int bl = tx * 16;
#pragma unroll
    for (int i = 0; i < 16; ++i) {
        const float pre = fmaf((float)iacc[i], sc, ba);
        tile[ty][bl + i] = 1.0f / (1.0f + __expf(-pre));
    }
    __syncthreads();

    // 512 local batch rows, 128 threads -> 4 rows each; 4 consecutive f32 (16B) per row
    const int t = ty * 32 + tx;
    const int bbase = blockIdx.x * 512;
#pragma unroll
    for (int r = 0; r < 4; ++r) {
        const int lb = t + r * 128;
        float4 w0;
        w0.x = tile[0][lb]; w0.y = tile[1][lb]; w0.z = tile[2][lb]; w0.w = tile[3][lb];
        *reinterpret_cast<float4*>(out + (size_t)(bbase + lb) * NOUT_ + o0) = w0;
    }
}

// ---------------------------------------------------------------------------
// kernel_launch: inputs in metadata order:
//   0: x (B,NIN) f32   1: W (L,N,K) f32   2: b (L,N) f32
//   3: W_out (NOUT,K) f32   4: b_out (NOUT,) f32
//   5: idx (L,N,K) i32      6: idx_out (NOUT,K) i32
// ---------------------------------------------------------------------------
extern "C" void kernel_launch(void* const* d_in, const int* in_sizes, int n_in,
                              void* d_out, int out_size) {
    const float* x     = (const float*)d_in[0];
    const float* W     = (const float*)d_in[1];
    const float* b     = (const float*)d_in[2];
    const float* W_out = (const float*)d_in[3];
    const float* b_out = (const float*)d_in[4];
    const int*   idx     = (const int*)d_in[5];
    const int*   idx_out = (const int*)d_in[6];
    float* out = (float*)d_out;

    prep_kernel<<<(NNEUR_ + 255) / 256, 256>>>(idx, W, b, idx_out, W_out, b_out);
    {
        dim3 blk(32, 32);
        dim3 grd(NIN_ / 32, B_ / 32);
        transpose_in_kernel<<<grd, blk>>>(x);
    }
    {
        dim3 blk(32, 4);
        dim3 grd(8, N_ / 4);   // 1024 blocks
        for (int l = 0; l < L_; ++l) layer_kernel<<<grd, blk>>>(l);
    }
    {
        dim3 blk(32, 4);
        dim3 grd(8, NOUT_ / 4);  // 512 blocks
        out_kernel<<<grd, blk>>>(out);
    }
}

// round 11
// speedup vs baseline: 1.3302x; 1.0234x over previous
#include <cuda_runtime.h>
#include <cstddef>

// Problem constants (fixed by the reference)
#define B_    4096
#define NIN_  512
#define L_    16
#define N_    512
#define K_    32
#define NOUT_ 256
#define NNEUR_ (L_ * N_ + NOUT_)      // 8448 total neurons
#define MAXP_  32                     // max pairs/neuron (<= 64 entries / 2)

// Unified byte buffer, feature-major rows of B_ bytes:
//   rows [0, 512):        x hi-plane  (u16 value >> 8)
//   rows [512, 1024):     x lo-plane  (u16 value & 0xFF)
//   rows [1024, 9216):    hidden activations u8 = round(255*sigmoid)
#define NROWS_ (2 * NIN_ + L_ * N_)   // 9216
__device__ unsigned char g_bytes[(size_t)NROWS_ * B_];

// Per-neuron preprocessed PAIR tables (prep_kernel fills these).
// Entry p: two feature byte-offsets + packed s16x2 weight codes [w0,w1].
// Padded with a zero pair at index np (off=0 -> harmless load, w=0).
__device__ int2  g_poff [(size_t)NNEUR_ * (MAXP_ + 1)];
__device__ int   g_pw   [(size_t)NNEUR_ * (MAXP_ + 1)];
__device__ int   g_np   [NNEUR_];                  // pair count
__device__ float g_scale[NNEUR_];                  // s/32767
__device__ float g_badj [NNEUR_];                  // bias + offset correction

__device__ __forceinline__ float tanhapx_(float x) {
    float r; asm("tanh.approx.f32 %0, %1;" : "=f"(r) : "f"(x)); return r;
}
__device__ __forceinline__ unsigned prmt_(unsigned a, unsigned b, unsigned sel) {
    unsigned d; asm("prmt.b32 %0, %1, %2, %3;" : "=r"(d) : "r"(a), "r"(b), "r"(sel));
    return d;
}
__device__ __forceinline__ void dp2a_lo_(int& acc, int a, unsigned b) {
    asm("dp2a.lo.s32.u32 %0, %1, %2, %0;" : "+r"(acc) : "r"(a), "r"(b));
}
__device__ __forceinline__ void dp2a_hi_(int& acc, int a, unsigned b) {
    asm("dp2a.hi.s32.u32 %0, %1, %2, %0;" : "+r"(acc) : "r"(a), "r"(b));
}

// Two feature words (4 batch bytes each) + s16x2 weight -> 8 MACs.
__device__ __forceinline__ void tpair2_(int* acc, unsigned A, unsigned Bw, int w01) {
    unsigned t0 = prmt_(A, Bw, 0x5140u);   // A0,B0,A1,B1
    unsigned t1 = prmt_(A, Bw, 0x7362u);   // A2,B2,A3,B3
    dp2a_lo_(acc[0], w01, t0);
    dp2a_hi_(acc[1], w01, t0);
    dp2a_lo_(acc[2], w01, t1);
    dp2a_hi_(acc[3], w01, t1);
}

// One loaded pair: a,b = uint4 rows of two features (16 batch elems).
__device__ __forceinline__ void compute_pair_(int* iacc, uint4 a, uint4 b, int w01) {
    tpair2_(iacc + 0,  a.x, b.x, w01);
    tpair2_(iacc + 4,  a.y, b.y, w01);
    tpair2_(iacc + 8,  a.z, b.z, w01);
    tpair2_(iacc + 12, a.w, b.w, w01);
}

// Software-pipelined gather: prefetch pair p+1 while computing pair p.
// Tables are padded (index np is a zero pair) so the prefetch is branchless.
__device__ __forceinline__ void gather_i8_(int* iacc, const int2* s_poff,
                                           const int* s_pw, int np, int q16) {
    const char* __restrict__ gb = reinterpret_cast<const char*>(g_bytes);
    int2 o = s_poff[0];
    int  w = s_pw[0];
    uint4 a = __ldg(reinterpret_cast<const uint4*>(gb + o.x + q16));
    uint4 b = __ldg(reinterpret_cast<const uint4*>(gb + o.y + q16));
    for (int p = 0; p < np; ++p) {
        const int2 o2 = s_poff[p + 1];
        const int  w2 = s_pw[p + 1];
        uint4 a2 = __ldg(reinterpret_cast<const uint4*>(gb + o2.x + q16));
        uint4 b2 = __ldg(reinterpret_cast<const uint4*>(gb + o2.y + q16));
        compute_pair_(iacc, a, b, w);
        a = a2; b = b2; w = w2;
    }
}

// ---------------------------------------------------------------------------
// Prep: per neuron, expand entries (x -> hi+lo planes), fold plane constants
// into s16 weight codes with per-neuron scale, pack into pairs (+1 zero pad).
// ---------------------------------------------------------------------------
__global__ void prep_kernel(const int* __restrict__ idx, const float* __restrict__ W,
                            const float* __restrict__ b,
                            const int* __restrict__ idx_out, const float* __restrict__ W_out,
                            const float* __restrict__ b_out) {
    const int t = blockIdx.x * blockDim.x + threadIdx.x;
    if (t >= NNEUR_) return;
    const int* ip; const float* wp; float bias;
    if (t < L_ * N_) { ip = idx + (size_t)t * K_;  wp = W + (size_t)t * K_;  bias = b[t]; }
    else { const int u = t - L_ * N_;
           ip = idx_out + (size_t)u * K_;  wp = W_out + (size_t)u * K_;  bias = b_out[u]; }

    int   eoff[2 * K_];
    float ecf [2 * K_];
    int ne = 0;
    float corr = 0.f;
    for (int k = 0; k < K_; ++k) {
        const int f = ip[k];
        const float w = wp[k];
        if (f < NIN_) {
            eoff[ne] = f * B_;             ecf[ne++] = w * (1.0f / 16.0f);    // hi plane
            eoff[ne] = (NIN_ + f) * B_;    ecf[ne++] = w * (1.0f / 4096.0f);  // lo plane
            corr -= 8.0f * w;
        } else {
            eoff[ne] = (2 * NIN_ + (f - NIN_)) * B_;  ecf[ne++] = w * (1.0f / 255.0f);
        }
    }
    float s = 0.f;
    for (int i = 0; i < ne; ++i) s = fmaxf(s, fabsf(ecf[i]));
    if (s == 0.f) s = 1.f;
    const float inv = 32767.0f / s;
    if (ne & 1) { eoff[ne] = 0; ecf[ne] = 0.f; ++ne; }
    const int np = ne >> 1;
    for (int p = 0; p < np; ++p) {
        int2 o2;
        o2.x = eoff[2 * p];
        o2.y = eoff[2 * p + 1];
        int q0 = __float2int_rn(ecf[2 * p] * inv);
        int q1 = __float2int_rn(ecf[2 * p + 1] * inv);
        q0 = max(-32767, min(32767, q0));
        q1 = max(-32767, min(32767, q1));
        g_poff[(size_t)t * (MAXP_ + 1) + p] = o2;
        g_pw  [(size_t)t * (MAXP_ + 1) + p] = (q1 << 16) | (q0 & 0xFFFF);
    }
    // zero-pad remaining entries including the prefetch sentinel
    for (int p = np; p <= MAXP_; ++p) {
        g_poff[(size_t)t * (MAXP_ + 1) + p] = make_int2(0, 0);
        g_pw  [(size_t)t * (MAXP_ + 1) + p] = 0;
    }
    g_np[t]    = np;
    g_scale[t] = s / 32767.0f;
    g_badj[t]  = bias + corr;
}

// ---------------------------------------------------------------------------
// Transpose x (B, NIN) f32 -> two u8 planes (feature-major), u16 = (x+8)*4096
// ---------------------------------------------------------------------------
__global__ void __launch_bounds__(1024) transpose_in_kernel(const float* __restrict__ x) {
    __shared__ float tile[32][33];
    const int f0 = blockIdx.x * 32;
    const int b0 = blockIdx.y * 32;
    tile[threadIdx.y][threadIdx.x] = x[(size_t)(b0 + threadIdx.y) * NIN_ + (f0 + threadIdx.x)];
    __syncthreads();
    const float xv = tile[threadIdx.x][threadIdx.y];
    float vf = fminf(fmaxf((xv + 8.0f) * 4096.0f, 0.0f), 65535.0f);
    const unsigned u = __float2uint_rn(vf);
    const int f = f0 + threadIdx.y;
    const int bb = b0 + threadIdx.x;
    g_bytes[(size_t)f * B_ + bb]           = (unsigned char)(u >> 8);
    g_bytes[(size_t)(NIN_ + f) * B_ + bb]  = (unsigned char)(u & 0xFF);
}

// ---------------------------------------------------------------------------
// One sparse layer. block (32,4): warp = one neuron, 32 tx x 16 batch = 512.
// grid (8, 128) = 1024 blocks of 128 threads.
// ---------------------------------------------------------------------------
__global__ void __launch_bounds__(128, 8) layer_kernel(int l) {
    __shared__ int2  s_poff[4][MAXP_ + 1];
    __shared__ int   s_pw  [4][MAXP_ + 1];
    __shared__ int   s_np[4];
    __shared__ float s_sc[4], s_ba[4];
    const int tx = threadIdx.x, ty = threadIdx.y;
    const int n  = blockIdx.y * 4 + ty;
    const int gn = l * N_ + n;

    s_poff[ty][tx] = g_poff[(size_t)gn * (MAXP_ + 1) + tx];
    s_pw  [ty][tx] = g_pw  [(size_t)gn * (MAXP_ + 1) + tx];
    if (tx == 0) {
        s_poff[ty][MAXP_] = g_poff[(size_t)gn * (MAXP_ + 1) + MAXP_];
        s_pw  [ty][MAXP_] = g_pw  [(size_t)gn * (MAXP_ + 1) + MAXP_];
        s_np[ty] = g_np[gn]; s_sc[ty] = g_scale[gn]; s_ba[ty] = g_badj[gn];
    }
    __syncthreads();

    const int q16 = (blockIdx.x * 32 + tx) * 16;

    int iacc[16];
#pragma unroll
    for (int i = 0; i < 16; ++i) iacc[i] = 0;

    gather_i8_(iacc, s_poff[ty], s_pw[ty], s_np[ty], q16);

    const float sc = s_sc[ty];
    const float ba = s_ba[ty];
    unsigned bytes[16];
#pragma unroll
    for (int i = 0; i < 16; ++i) {
        const float pre = fmaf((float)iacc[i], sc, ba);
        const float th  = tanhapx_(0.5f * pre);                 // sigmoid = .5+.5*tanh(v/2)
        bytes[i] = __float2uint_rn(fmaf(th, 127.5f, 127.5f));   // round(255*sigmoid)
    }
    uint4 o;
    unsigned* ow = &o.x;
#pragma unroll
    for (int i = 0; i < 4; ++i) {
        unsigned lo = __byte_perm(bytes[4 * i],     bytes[4 * i + 1], 0x0040);
        unsigned hi = __byte_perm(bytes[4 * i + 2], bytes[4 * i + 3], 0x0040);
        ow[i] = __byte_perm(lo, hi, 0x5410);
    }
    *reinterpret_cast<uint4*>(g_bytes + (size_t)(2 * NIN_ + gn) * B_ + q16) = o;
}

// ---------------------------------------------------------------------------
// Output layer. block (32,4), grid (8, 64) = 512 blocks. Exact sigmoid,
// f32 out, smem transpose so each thread stores full 16B sectors.
// ---------------------------------------------------------------------------
__global__ void __launch_bounds__(128, 8) out_kernel(float* __restrict__ out) {
    __shared__ int2  s_poff[4][MAXP_ + 1];
    __shared__ int   s_pw  [4][MAXP_ + 1];
    __shared__ int   s_np[4];
    __shared__ float s_sc[4], s_ba[4];
    __shared__ float tile[4][512];
    const int tx = threadIdx.x, ty = threadIdx.y;
    const int o0 = blockIdx.y * 4;
    const int o  = o0 + ty;
    const int gn = L_ * N_ + o;

    s_poff[ty][tx] = g_poff[(size_t)gn * (MAXP_ + 1) + tx];
    s_pw  [ty][tx] = g_pw  [(size_t)gn * (MAXP_ + 1) + tx];
    if (tx == 0) {
        s_poff[ty][MAXP_] = g_poff[(size_t)gn * (MAXP_ + 1) + MAXP_];
        s_pw  [ty][MAXP_] = g_pw  [(size_t)gn * (MAXP_ + 1) + MAXP_];
        s_np[ty] = g_np[gn]; s_sc[ty] = g_scale[gn]; s_ba[ty] = g_badj[gn];
    }
    __syncthreads();

    const int q16 = (blockIdx.x * 32 + tx) * 16;

    int iacc[16];
#pragma unroll
    for (int i = 0; i < 16; ++i) iacc[i] = 0;

    gather_i8_(iacc, s_poff[ty], s_pw[ty], s_np[ty], q16);

    const float sc = s_sc[ty];
    const float ba = s_ba[ty];
    const int bl = tx * 16;
#pragma unroll
    for (int i = 0; i < 16; ++i) {
        const float pre = fmaf((float)iacc[i], sc, ba);
        tile[ty][bl + i] = 1.0f / (1.0f + __expf(-pre));
    }
    __syncthreads();

    // 512 local batch rows, 128 threads -> 4 rows each; 4 consecutive f32 (16B) per row
    const int t = ty * 32 + tx;
    const int bbase = blockIdx.x * 512;
#pragma unroll
    for (int r = 0; r < 4; ++r) {
        const int lb = t + r * 128;
        float4 w0;
        w0.x = tile[0][lb]; w0.y = tile[1][lb]; w0.z = tile[2][lb]; w0.w = tile[3][lb];
        *reinterpret_cast<float4*>(out + (size_t)(bbase + lb) * NOUT_ + o0) = w0;
    }
}

// ---------------------------------------------------------------------------
// kernel_launch: inputs in metadata order:
//   0: x (B,NIN) f32   1: W (L,N,K) f32   2: b (L,N) f32
//   3: W_out (NOUT,K) f32   4: b_out (NOUT,) f32
//   5: idx (L,N,K) i32      6: idx_out (NOUT,K) i32
// ---------------------------------------------------------------------------
extern "C" void kernel_launch(void* const* d_in, const int* in_sizes, int n_in,
                              void* d_out, int out_size) {
    const float* x     = (const float*)d_in[0];
    const float* W     = (const float*)d_in[1];
    const float* b     = (const float*)d_in[2];
    const float* W_out = (const float*)d_in[3];
    const float* b_out = (const float*)d_in[4];
    const int*   idx     = (const int*)d_in[5];
    const int*   idx_out = (const int*)d_in[6];
    float* out = (float*)d_out;

    prep_kernel<<<(NNEUR_ + 255) / 256, 256>>>(idx, W, b, idx_out, W_out, b_out);
    {
        dim3 blk(32, 32);
        dim3 grd(NIN_ / 32, B_ / 32);
        transpose_in_kernel<<<grd, blk>>>(x);
    }
    {
        dim3 blk(32, 4);
        dim3 grd(8, N_ / 4);   // 1024 blocks
        for (int l = 0; l < L_; ++l) layer_kernel<<<grd, blk>>>(l);
    }
    {
        dim3 blk(32, 4);
        dim3 grd(8, NOUT_ / 4);  // 512 blocks
        out_kernel<<<grd, blk>>>(out);
    }
}